// round 9
// baseline (speedup 1.0000x reference)
#include <cuda_runtime.h>
#include <cuda_bf16.h>
#include <cuda_fp16.h>
#include <cstdint>

#define NQ 16384
#define NK 16384
#define DIM 256
#define DV 256
#define NTILES 128  // NK / 128 column tiles in qk

// ---------------- scratch (static device arrays; no allocations) ----------------
__device__ __nv_bfloat16 g_Qh[NQ * DIM];
__device__ __nv_bfloat16 g_Ql[NQ * DIM];
__device__ __nv_bfloat16 g_Kh[NK * DIM];
__device__ __nv_bfloat16 g_Kl[NK * DIM];
__device__ __half g_Vf[NK * DV];
__device__ float g_pm[(size_t)NQ * NTILES];   // per-(row,tile) partial max
__device__ float g_pl[(size_t)NQ * NTILES];   // per-(row,tile) partial exp-sum
__device__ float g_rm[NQ];                    // per-row max
__device__ float g_rinv[NQ];                  // per-row 1/sum

// ---------------- helpers ----------------
__device__ __forceinline__ unsigned smem_u32(const void* p) {
    return (unsigned)__cvta_generic_to_shared(p);
}
__device__ __forceinline__ void cp16(void* dst, const void* src) {
    unsigned d = smem_u32(dst);
    asm volatile("cp.async.cg.shared.global [%0], [%1], 16;" :: "r"(d), "l"(src));
}
__device__ __forceinline__ void cp_commit() {
    asm volatile("cp.async.commit_group;");
}
template <int N>
__device__ __forceinline__ void cp_wait() {
    asm volatile("cp.async.wait_group %0;" :: "n"(N));
}
__device__ __forceinline__ void ldsm_x4(uint32_t* r, unsigned addr) {
    asm volatile("ldmatrix.sync.aligned.m8n8.x4.shared.b16 {%0,%1,%2,%3}, [%4];"
                 : "=r"(r[0]), "=r"(r[1]), "=r"(r[2]), "=r"(r[3]) : "r"(addr));
}
__device__ __forceinline__ void ldsm_x2(uint32_t* r, unsigned addr) {
    asm volatile("ldmatrix.sync.aligned.m8n8.x2.shared.b16 {%0,%1}, [%2];"
                 : "=r"(r[0]), "=r"(r[1]) : "r"(addr));
}
__device__ __forceinline__ void ldsm_x2_trans(uint32_t* r, unsigned addr) {
    asm volatile("ldmatrix.sync.aligned.m8n8.x2.trans.shared.b16 {%0,%1}, [%2];"
                 : "=r"(r[0]), "=r"(r[1]) : "r"(addr));
}
__device__ __forceinline__ void mma_bf16(float* c, const uint32_t* a, const uint32_t* b) {
    asm volatile(
        "mma.sync.aligned.m16n8k16.row.col.f32.bf16.bf16.f32 "
        "{%0,%1,%2,%3},{%4,%5,%6,%7},{%8,%9},{%0,%1,%2,%3};"
        : "+f"(c[0]), "+f"(c[1]), "+f"(c[2]), "+f"(c[3])
        : "r"(a[0]), "r"(a[1]), "r"(a[2]), "r"(a[3]), "r"(b[0]), "r"(b[1]));
}
__device__ __forceinline__ void mma_fp16(float* c, const uint32_t* a, const uint32_t* b) {
    asm volatile(
        "mma.sync.aligned.m16n8k16.row.col.f32.f16.f16.f32 "
        "{%0,%1,%2,%3},{%4,%5,%6,%7},{%8,%9},{%0,%1,%2,%3};"
        : "+f"(c[0]), "+f"(c[1]), "+f"(c[2]), "+f"(c[3])
        : "r"(a[0]), "r"(a[1]), "r"(a[2]), "r"(a[3]), "r"(b[0]), "r"(b[1]));
}

// ---------------- kernel 1: splits (Q,K -> bf16 hi/lo; V -> fp16) ----------------
__global__ void split_all_kernel(const float* __restrict__ Q,
                                 const float* __restrict__ K,
                                 const float* __restrict__ V) {
    int i = blockIdx.x * blockDim.x + threadIdx.x;
    if (i < NQ * DIM) {
        float q = Q[i];
        __nv_bfloat16 qh = __float2bfloat16(q);
        g_Qh[i] = qh;
        g_Ql[i] = __float2bfloat16(q - __bfloat162float(qh));
        float k = K[i];
        __nv_bfloat16 kh = __float2bfloat16(k);
        g_Kh[i] = kh;
        g_Kl[i] = __float2bfloat16(k - __bfloat162float(kh));
        g_Vf[i] = __float2half_rn(V[i]);
    }
}

// ---------------- kernel 2: S = Q K^T (raw scores) + per-tile softmax stats ----------------
// CTA tile 128x128, 512 threads, 16 warps 4(m)x4(n), warp tile 32x32. Sync loads (R4-proven).
// S = Qh*Kh + Qh*Kl + Ql*Kh (error-compensated bf16).
#define QKS 72
#define QK_A (128 * QKS)

__global__ __launch_bounds__(512, 1) void qk_kernel(float* __restrict__ W) {
    extern __shared__ __nv_bfloat16 sm[];
    __shared__ float s_rmax[128][4];
    __shared__ float s_rsum[128][4];
    __nv_bfloat16* sQh = sm;
    __nv_bfloat16* sQl = sm + QK_A;
    __nv_bfloat16* sKh = sm + 2 * QK_A;
    __nv_bfloat16* sKl = sm + 3 * QK_A;

    const int tid = threadIdx.x;
    const int lane = tid & 31, w = tid >> 5;
    const int wm = w >> 2, wn = w & 3;
    const int qBase = blockIdx.y * 128;
    const int kBase = blockIdx.x * 128;

    float acc[2][4][4];
#pragma unroll
    for (int mi = 0; mi < 2; mi++)
#pragma unroll
        for (int ni = 0; ni < 4; ni++)
#pragma unroll
            for (int j = 0; j < 4; j++) acc[mi][ni][j] = 0.f;

    for (int kc = 0; kc < DIM; kc += 64) {
#pragma unroll
        for (int it = 0; it < 2; it++) {
            int idx = it * 512 + tid;
            int row = idx >> 3, cv = (idx & 7) << 3;
            size_t gq = (size_t)(qBase + row) * DIM + kc + cv;
            size_t gk = (size_t)(kBase + row) * DIM + kc + cv;
            *(uint4*)&sQh[row * QKS + cv] = *(const uint4*)&g_Qh[gq];
            *(uint4*)&sQl[row * QKS + cv] = *(const uint4*)&g_Ql[gq];
            *(uint4*)&sKh[row * QKS + cv] = *(const uint4*)&g_Kh[gk];
            *(uint4*)&sKl[row * QKS + cv] = *(const uint4*)&g_Kl[gk];
        }
        __syncthreads();

#pragma unroll
        for (int ks = 0; ks < 4; ks++) {
            const int k0 = ks * 16;
            uint32_t ah[2][4], al[2][4], bh[4][2], bl[4][2];
#pragma unroll
            for (int mi = 0; mi < 2; mi++) {
                int m0 = wm * 32 + mi * 16;
                int mat = lane >> 3;
                int r = m0 + ((mat & 1) << 3) + (lane & 7);
                int c = k0 + ((mat >> 1) << 3);
                ldsm_x4(ah[mi], smem_u32(&sQh[r * QKS + c]));
                ldsm_x4(al[mi], smem_u32(&sQl[r * QKS + c]));
            }
#pragma unroll
            for (int ni = 0; ni < 4; ni++) {
                int n0 = wn * 32 + ni * 8;
                int mat = (lane >> 3) & 1;
                int r = n0 + (lane & 7);
                int c = k0 + (mat << 3);
                ldsm_x2(bh[ni], smem_u32(&sKh[r * QKS + c]));
                ldsm_x2(bl[ni], smem_u32(&sKl[r * QKS + c]));
            }
#pragma unroll
            for (int mi = 0; mi < 2; mi++)
#pragma unroll
                for (int ni = 0; ni < 4; ni++) {
                    mma_bf16(acc[mi][ni], ah[mi], bh[ni]);
                    mma_bf16(acc[mi][ni], ah[mi], bl[ni]);
                    mma_bf16(acc[mi][ni], al[mi], bh[ni]);
                }
        }
        __syncthreads();
    }

    // store raw scores
#pragma unroll
    for (int mi = 0; mi < 2; mi++) {
        int r0 = qBase + wm * 32 + mi * 16 + (lane >> 2);
#pragma unroll
        for (int ni = 0; ni < 4; ni++) {
            int c0 = kBase + wn * 32 + ni * 8 + ((lane & 3) << 1);
            *(float2*)&W[(size_t)r0 * NK + c0] = make_float2(acc[mi][ni][0], acc[mi][ni][1]);
            *(float2*)&W[(size_t)(r0 + 8) * NK + c0] = make_float2(acc[mi][ni][2], acc[mi][ni][3]);
        }
    }

    // ---- per-(row, tile) stats: partial max + partial exp-sum (R3-proven logic) ----
#pragma unroll
    for (int mi = 0; mi < 2; mi++) {
        float m0 = -3.0e38f, m1 = -3.0e38f;
#pragma unroll
        for (int ni = 0; ni < 4; ni++) {
            m0 = fmaxf(m0, fmaxf(acc[mi][ni][0], acc[mi][ni][1]));
            m1 = fmaxf(m1, fmaxf(acc[mi][ni][2], acc[mi][ni][3]));
        }
        m0 = fmaxf(m0, __shfl_xor_sync(0xffffffffu, m0, 1));
        m0 = fmaxf(m0, __shfl_xor_sync(0xffffffffu, m0, 2));
        m1 = fmaxf(m1, __shfl_xor_sync(0xffffffffu, m1, 1));
        m1 = fmaxf(m1, __shfl_xor_sync(0xffffffffu, m1, 2));
        int rl = wm * 32 + mi * 16 + (lane >> 2);
        if ((lane & 3) == 0) {
            s_rmax[rl][wn] = m0;
            s_rmax[rl + 8][wn] = m1;
        }
    }
    __syncthreads();
#pragma unroll
    for (int mi = 0; mi < 2; mi++) {
        int rl = wm * 32 + mi * 16 + (lane >> 2);
        float tm0 = fmaxf(fmaxf(s_rmax[rl][0], s_rmax[rl][1]),
                          fmaxf(s_rmax[rl][2], s_rmax[rl][3]));
        float tm1 = fmaxf(fmaxf(s_rmax[rl + 8][0], s_rmax[rl + 8][1]),
                          fmaxf(s_rmax[rl + 8][2], s_rmax[rl + 8][3]));
        float s0 = 0.f, s1 = 0.f;
#pragma unroll
        for (int ni = 0; ni < 4; ni++) {
            s0 += __expf(acc[mi][ni][0] - tm0) + __expf(acc[mi][ni][1] - tm0);
            s1 += __expf(acc[mi][ni][2] - tm1) + __expf(acc[mi][ni][3] - tm1);
        }
        s0 += __shfl_xor_sync(0xffffffffu, s0, 1);
        s0 += __shfl_xor_sync(0xffffffffu, s0, 2);
        s1 += __shfl_xor_sync(0xffffffffu, s1, 1);
        s1 += __shfl_xor_sync(0xffffffffu, s1, 2);
        if ((lane & 3) == 0) {
            s_rsum[rl][wn] = s0;
            s_rsum[rl + 8][wn] = s1;
        }
    }
    __syncthreads();
    if (wn == 0 && (lane & 3) == 0) {
        const int tileCol = blockIdx.x;
#pragma unroll
        for (int mi = 0; mi < 2; mi++) {
            int rl = wm * 32 + mi * 16 + (lane >> 2);
#pragma unroll
            for (int half = 0; half < 2; half++) {
                int r = rl + half * 8;
                float tm = fmaxf(fmaxf(s_rmax[r][0], s_rmax[r][1]),
                                 fmaxf(s_rmax[r][2], s_rmax[r][3]));
                float tl = s_rsum[r][0] + s_rsum[r][1] + s_rsum[r][2] + s_rsum[r][3];
                g_pm[(size_t)(qBase + r) * NTILES + tileCol] = tm;
                g_pl[(size_t)(qBase + r) * NTILES + tileCol] = tl;
            }
        }
    }
}

// ---------------- kernel 3: combine partial stats -> per-row (max, 1/sum) ----------------
__global__ void combine_kernel() {
    int row = blockIdx.x * 8 + (threadIdx.x >> 5);
    int lane = threadIdx.x & 31;
    float mv[4], lv[4];
    float m = -3.0e38f;
#pragma unroll
    for (int j = 0; j < 4; j++) {
        mv[j] = g_pm[(size_t)row * NTILES + lane * 4 + j];
        lv[j] = g_pl[(size_t)row * NTILES + lane * 4 + j];
        m = fmaxf(m, mv[j]);
    }
#pragma unroll
    for (int o = 16; o; o >>= 1) m = fmaxf(m, __shfl_xor_sync(0xffffffffu, m, o));
    float l = 0.f;
#pragma unroll
    for (int j = 0; j < 4; j++) l += lv[j] * __expf(mv[j] - m);
#pragma unroll
    for (int o = 16; o; o >>= 1) l += __shfl_xor_sync(0xffffffffu, l, o);
    if (lane == 0) {
        g_rm[row] = m;
        g_rinv[row] = 1.0f / l;
    }
}

// ---------------- kernel 4: normalize (exp) + write W + X = W V (fp16 single pass) ----------------
// CTA tile 64(m) x 256(n); K-chunks of 64. V fp16 double-buffered via cp.async;
// raw S chunk -> exp*inv -> W output + fp16 smem. 2 CTAs/SM.
#define PWS 72
#define PVS 264

__global__ __launch_bounds__(256, 2) void pv_kernel(float* __restrict__ S,
                                                    float* __restrict__ X) {
    extern __shared__ __half smh[];
    __half* sWf = smh;                 // 64 x 72
    __half* sV = smh + 64 * PWS;       // 2 stages x 64 x 264
    __shared__ float s_m[64], s_inv[64];

    const int tid = threadIdx.x;
    const int lane = tid & 31, w = tid >> 5;
    const int wm = w >> 2, wn = w & 3;
    const int mBase = blockIdx.x * 64;

    float acc[2][8][4];
#pragma unroll
    for (int mi = 0; mi < 2; mi++)
#pragma unroll
        for (int ni = 0; ni < 8; ni++)
#pragma unroll
            for (int j = 0; j < 4; j++) acc[mi][ni][j] = 0.f;

    auto loadV = [&](int s, int k0) {
        __half* vf = sV + s * 64 * PVS;
#pragma unroll
        for (int it = 0; it < 8; it++) {
            int idx = it * 256 + tid;
            int row = idx >> 5, cv = (idx & 31) << 3;
            cp16(vf + row * PVS + cv, g_Vf + (size_t)(k0 + row) * DV + cv);
        }
        cp_commit();
    };

    if (tid < 64) {
        s_m[tid] = g_rm[mBase + tid];
        s_inv[tid] = g_rinv[mBase + tid];
    }
    loadV(0, 0);
    __syncthreads();

    for (int i = 0; i < NK / 64; i++) {
        const int k0 = i * 64;
        if (i < NK / 64 - 1) loadV((i + 1) & 1, k0 + 64);

        // raw S chunk 64x64 -> exp*inv -> W output (fp32) + fp16 smem
#pragma unroll
        for (int it = 0; it < 4; it++) {
            int idx = it * 256 + tid;
            int row = idx >> 4, cv = (idx & 15) << 2;
            float m = s_m[row], inv = s_inv[row];
            float4 t = *(const float4*)&S[(size_t)(mBase + row) * NK + k0 + cv];
            t.x = __expf(t.x - m) * inv;
            t.y = __expf(t.y - m) * inv;
            t.z = __expf(t.z - m) * inv;
            t.w = __expf(t.w - m) * inv;
            *(float4*)&S[(size_t)(mBase + row) * NK + k0 + cv] = t;
            __half2* p = (__half2*)&sWf[row * PWS + cv];
            p[0] = __halves2half2(__float2half_rn(t.x), __float2half_rn(t.y));
            p[1] = __halves2half2(__float2half_rn(t.z), __float2half_rn(t.w));
        }

        if (i < NK / 64 - 1) cp_wait<1>();
        else cp_wait<0>();
        __syncthreads();

        const __half* vf = sV + (i & 1) * 64 * PVS;

#pragma unroll
        for (int ks = 0; ks < 4; ks++) {
            int kk = ks * 16;
            uint32_t a[2][4], b[8][2];
#pragma unroll
            for (int mi = 0; mi < 2; mi++) {
                int m0 = wm * 32 + mi * 16;
                int mat = lane >> 3;
                int r = m0 + ((mat & 1) << 3) + (lane & 7);
                int c = kk + ((mat >> 1) << 3);
                ldsm_x4(a[mi], smem_u32(&sWf[r * PWS + c]));
            }
#pragma unroll
            for (int ni = 0; ni < 8; ni++) {
                int n0 = wn * 64 + ni * 8;
                int mat = (lane >> 3) & 1;
                int r = kk + (mat << 3) + (lane & 7);
                ldsm_x2_trans(b[ni], smem_u32(&vf[r * PVS + n0]));
            }
#pragma unroll
            for (int mi = 0; mi < 2; mi++)
#pragma unroll
                for (int ni = 0; ni < 8; ni++)
                    mma_fp16(acc[mi][ni], a[mi], b[ni]);
        }
        __syncthreads();
    }

#pragma unroll
    for (int mi = 0; mi < 2; mi++) {
        int r0 = mBase + wm * 32 + mi * 16 + (lane >> 2);
#pragma unroll
        for (int ni = 0; ni < 8; ni++) {
            int c0 = wn * 64 + ni * 8 + ((lane & 3) << 1);
            *(float2*)&X[(size_t)r0 * DV + c0] = make_float2(acc[mi][ni][0], acc[mi][ni][1]);
            *(float2*)&X[(size_t)(r0 + 8) * DV + c0] = make_float2(acc[mi][ni][2], acc[mi][ni][3]);
        }
    }
}

// ---------------- launcher ----------------
extern "C" void kernel_launch(void* const* d_in, const int* in_sizes, int n_in,
                              void* d_out, int out_size) {
    const float* Q = (const float*)d_in[0];
    const float* K = (const float*)d_in[1];
    const float* V = (const float*)d_in[2];
    float* X = (float*)d_out;                    // [NQ, DV]
    float* W = (float*)d_out + (size_t)NQ * DV;  // [NQ, NK]

    const int qk_smem = 4 * QK_A * 2;                      // 73728 B
    const int pv_smem = (64 * PWS + 2 * 64 * PVS) * 2;     // 76800 B
    cudaFuncSetAttribute(qk_kernel, cudaFuncAttributeMaxDynamicSharedMemorySize, qk_smem);
    cudaFuncSetAttribute(pv_kernel, cudaFuncAttributeMaxDynamicSharedMemorySize, pv_smem);

    split_all_kernel<<<(NQ * DIM + 255) / 256, 256>>>(Q, K, V);

    dim3 qkGrid(NK / 128, NQ / 128);
    qk_kernel<<<qkGrid, 512, qk_smem>>>(W);

    combine_kernel<<<NQ / 8, 256>>>();

    pv_kernel<<<NQ / 64, 256, pv_smem>>>(W, X);
}

// round 13
// speedup vs baseline: 1.0930x; 1.0930x over previous
#include <cuda_runtime.h>
#include <cuda_bf16.h>
#include <cuda_fp16.h>
#include <cstdint>

#define NQ 16384
#define NK 16384
#define DIM 256
#define DV 256
#define NTILES 128  // NK / 128 column tiles in qk

// ---------------- scratch (static device arrays; no allocations) ----------------
__device__ __nv_bfloat16 g_Qh[NQ * DIM];
__device__ __nv_bfloat16 g_Ql[NQ * DIM];
__device__ __nv_bfloat16 g_Kh[NK * DIM];
__device__ __nv_bfloat16 g_Kl[NK * DIM];
__device__ __half g_Vf[NK * DV];
__device__ float g_pm[(size_t)NQ * NTILES];   // per-(row,tile) partial max
__device__ float g_pl[(size_t)NQ * NTILES];   // per-(row,tile) partial exp-sum
__device__ unsigned g_cnt[NQ / 128];          // per-row-block completion counters

// ---------------- helpers ----------------
__device__ __forceinline__ unsigned smem_u32(const void* p) {
    return (unsigned)__cvta_generic_to_shared(p);
}
__device__ __forceinline__ void cp16(void* dst, const void* src) {
    unsigned d = smem_u32(dst);
    asm volatile("cp.async.cg.shared.global [%0], [%1], 16;" :: "r"(d), "l"(src));
}
__device__ __forceinline__ void cp_commit() {
    asm volatile("cp.async.commit_group;");
}
template <int N>
__device__ __forceinline__ void cp_wait() {
    asm volatile("cp.async.wait_group %0;" :: "n"(N));
}
__device__ __forceinline__ void ldsm_x4(uint32_t* r, unsigned addr) {
    asm volatile("ldmatrix.sync.aligned.m8n8.x4.shared.b16 {%0,%1,%2,%3}, [%4];"
                 : "=r"(r[0]), "=r"(r[1]), "=r"(r[2]), "=r"(r[3]) : "r"(addr));
}
__device__ __forceinline__ void ldsm_x2(uint32_t* r, unsigned addr) {
    asm volatile("ldmatrix.sync.aligned.m8n8.x2.shared.b16 {%0,%1}, [%2];"
                 : "=r"(r[0]), "=r"(r[1]) : "r"(addr));
}
__device__ __forceinline__ void ldsm_x2_trans(uint32_t* r, unsigned addr) {
    asm volatile("ldmatrix.sync.aligned.m8n8.x2.trans.shared.b16 {%0,%1}, [%2];"
                 : "=r"(r[0]), "=r"(r[1]) : "r"(addr));
}
__device__ __forceinline__ void mma_bf16(float* c, const uint32_t* a, const uint32_t* b) {
    asm volatile(
        "mma.sync.aligned.m16n8k16.row.col.f32.bf16.bf16.f32 "
        "{%0,%1,%2,%3},{%4,%5,%6,%7},{%8,%9},{%0,%1,%2,%3};"
        : "+f"(c[0]), "+f"(c[1]), "+f"(c[2]), "+f"(c[3])
        : "r"(a[0]), "r"(a[1]), "r"(a[2]), "r"(a[3]), "r"(b[0]), "r"(b[1]));
}
__device__ __forceinline__ void mma_fp16(float* c, const uint32_t* a, const uint32_t* b) {
    asm volatile(
        "mma.sync.aligned.m16n8k16.row.col.f32.f16.f16.f32 "
        "{%0,%1,%2,%3},{%4,%5,%6,%7},{%8,%9},{%0,%1,%2,%3};"
        : "+f"(c[0]), "+f"(c[1]), "+f"(c[2]), "+f"(c[3])
        : "r"(a[0]), "r"(a[1]), "r"(a[2]), "r"(a[3]), "r"(b[0]), "r"(b[1]));
}

// ---------------- kernel 1: splits + counter reset ----------------
__global__ void split_all_kernel(const float* __restrict__ Q,
                                 const float* __restrict__ K,
                                 const float* __restrict__ V) {
    int i = blockIdx.x * blockDim.x + threadIdx.x;
    if (blockIdx.x == 0 && threadIdx.x < NQ / 128) g_cnt[threadIdx.x] = 0u;
    if (i < NQ * DIM) {
        float q = Q[i];
        __nv_bfloat16 qh = __float2bfloat16(q);
        g_Qh[i] = qh;
        g_Ql[i] = __float2bfloat16(q - __bfloat162float(qh));
        float k = K[i];
        __nv_bfloat16 kh = __float2bfloat16(k);
        g_Kh[i] = kh;
        g_Kl[i] = __float2bfloat16(k - __bfloat162float(kh));
        g_Vf[i] = __float2half_rn(V[i]);
    }
}

// ---------------- kernel 2: S = Q K^T + stats + distributed fused softmax tail ----------------
// CTA tile 128x128, 512 threads, 16 warps 4(m)x4(n), warp tile 32x32 (R4-proven core).
// S = Qh*Kh + Qh*Kl + Ql*Kh (error-compensated bf16).
// Tail: last 8 finishers of each 128-row block normalize 16 rows each in place.
#define QKS 72
#define QK_A (128 * QKS)

__global__ __launch_bounds__(512, 1) void qk_kernel(float* __restrict__ W) {
    extern __shared__ __nv_bfloat16 sm[];
    __shared__ float s_rmax[128][4];
    __shared__ float s_rsum[128][4];
    __shared__ unsigned s_ticket;
    __nv_bfloat16* sQh = sm;
    __nv_bfloat16* sQl = sm + QK_A;
    __nv_bfloat16* sKh = sm + 2 * QK_A;
    __nv_bfloat16* sKl = sm + 3 * QK_A;

    const int tid = threadIdx.x;
    const int lane = tid & 31, w = tid >> 5;
    const int wm = w >> 2, wn = w & 3;
    const int qBase = blockIdx.y * 128;
    const int kBase = blockIdx.x * 128;

    float acc[2][4][4];
#pragma unroll
    for (int mi = 0; mi < 2; mi++)
#pragma unroll
        for (int ni = 0; ni < 4; ni++)
#pragma unroll
            for (int j = 0; j < 4; j++) acc[mi][ni][j] = 0.f;

    for (int kc = 0; kc < DIM; kc += 64) {
#pragma unroll
        for (int it = 0; it < 2; it++) {
            int idx = it * 512 + tid;
            int row = idx >> 3, cv = (idx & 7) << 3;
            size_t gq = (size_t)(qBase + row) * DIM + kc + cv;
            size_t gk = (size_t)(kBase + row) * DIM + kc + cv;
            *(uint4*)&sQh[row * QKS + cv] = *(const uint4*)&g_Qh[gq];
            *(uint4*)&sQl[row * QKS + cv] = *(const uint4*)&g_Ql[gq];
            *(uint4*)&sKh[row * QKS + cv] = *(const uint4*)&g_Kh[gk];
            *(uint4*)&sKl[row * QKS + cv] = *(const uint4*)&g_Kl[gk];
        }
        __syncthreads();

#pragma unroll
        for (int ks = 0; ks < 4; ks++) {
            const int k0 = ks * 16;
            uint32_t ah[2][4], al[2][4], bh[4][2], bl[4][2];
#pragma unroll
            for (int mi = 0; mi < 2; mi++) {
                int m0 = wm * 32 + mi * 16;
                int mat = lane >> 3;
                int r = m0 + ((mat & 1) << 3) + (lane & 7);
                int c = k0 + ((mat >> 1) << 3);
                ldsm_x4(ah[mi], smem_u32(&sQh[r * QKS + c]));
                ldsm_x4(al[mi], smem_u32(&sQl[r * QKS + c]));
            }
#pragma unroll
            for (int ni = 0; ni < 4; ni++) {
                int n0 = wn * 32 + ni * 8;
                int mat = (lane >> 3) & 1;
                int r = n0 + (lane & 7);
                int c = k0 + (mat << 3);
                ldsm_x2(bh[ni], smem_u32(&sKh[r * QKS + c]));
                ldsm_x2(bl[ni], smem_u32(&sKl[r * QKS + c]));
            }
#pragma unroll
            for (int mi = 0; mi < 2; mi++)
#pragma unroll
                for (int ni = 0; ni < 4; ni++) {
                    mma_bf16(acc[mi][ni], ah[mi], bh[ni]);
                    mma_bf16(acc[mi][ni], ah[mi], bl[ni]);
                    mma_bf16(acc[mi][ni], al[mi], bh[ni]);
                }
        }
        __syncthreads();
    }

    // store raw scores
#pragma unroll
    for (int mi = 0; mi < 2; mi++) {
        int r0 = qBase + wm * 32 + mi * 16 + (lane >> 2);
#pragma unroll
        for (int ni = 0; ni < 4; ni++) {
            int c0 = kBase + wn * 32 + ni * 8 + ((lane & 3) << 1);
            *(float2*)&W[(size_t)r0 * NK + c0] = make_float2(acc[mi][ni][0], acc[mi][ni][1]);
            *(float2*)&W[(size_t)(r0 + 8) * NK + c0] = make_float2(acc[mi][ni][2], acc[mi][ni][3]);
        }
    }

    // ---- per-(row, tile) stats (R7-proven) ----
#pragma unroll
    for (int mi = 0; mi < 2; mi++) {
        float m0 = -3.0e38f, m1 = -3.0e38f;
#pragma unroll
        for (int ni = 0; ni < 4; ni++) {
            m0 = fmaxf(m0, fmaxf(acc[mi][ni][0], acc[mi][ni][1]));
            m1 = fmaxf(m1, fmaxf(acc[mi][ni][2], acc[mi][ni][3]));
        }
        m0 = fmaxf(m0, __shfl_xor_sync(0xffffffffu, m0, 1));
        m0 = fmaxf(m0, __shfl_xor_sync(0xffffffffu, m0, 2));
        m1 = fmaxf(m1, __shfl_xor_sync(0xffffffffu, m1, 1));
        m1 = fmaxf(m1, __shfl_xor_sync(0xffffffffu, m1, 2));
        int rl = wm * 32 + mi * 16 + (lane >> 2);
        if ((lane & 3) == 0) {
            s_rmax[rl][wn] = m0;
            s_rmax[rl + 8][wn] = m1;
        }
    }
    __syncthreads();
#pragma unroll
    for (int mi = 0; mi < 2; mi++) {
        int rl = wm * 32 + mi * 16 + (lane >> 2);
        float tm0 = fmaxf(fmaxf(s_rmax[rl][0], s_rmax[rl][1]),
                          fmaxf(s_rmax[rl][2], s_rmax[rl][3]));
        float tm1 = fmaxf(fmaxf(s_rmax[rl + 8][0], s_rmax[rl + 8][1]),
                          fmaxf(s_rmax[rl + 8][2], s_rmax[rl + 8][3]));
        float s0 = 0.f, s1 = 0.f;
#pragma unroll
        for (int ni = 0; ni < 4; ni++) {
            s0 += __expf(acc[mi][ni][0] - tm0) + __expf(acc[mi][ni][1] - tm0);
            s1 += __expf(acc[mi][ni][2] - tm1) + __expf(acc[mi][ni][3] - tm1);
        }
        s0 += __shfl_xor_sync(0xffffffffu, s0, 1);
        s0 += __shfl_xor_sync(0xffffffffu, s0, 2);
        s1 += __shfl_xor_sync(0xffffffffu, s1, 1);
        s1 += __shfl_xor_sync(0xffffffffu, s1, 2);
        if ((lane & 3) == 0) {
            s_rsum[rl][wn] = s0;
            s_rsum[rl + 8][wn] = s1;
        }
    }
    __syncthreads();
    if (wn == 0 && (lane & 3) == 0) {
        const int tileCol = blockIdx.x;
#pragma unroll
        for (int mi = 0; mi < 2; mi++) {
            int rl = wm * 32 + mi * 16 + (lane >> 2);
#pragma unroll
            for (int half = 0; half < 2; half++) {
                int r = rl + half * 8;
                float tm = fmaxf(fmaxf(s_rmax[r][0], s_rmax[r][1]),
                                 fmaxf(s_rmax[r][2], s_rmax[r][3]));
                float tl = s_rsum[r][0] + s_rsum[r][1] + s_rsum[r][2] + s_rsum[r][3];
                g_pm[(size_t)(qBase + r) * NTILES + tileCol] = tm;
                g_pl[(size_t)(qBase + r) * NTILES + tileCol] = tl;
            }
        }
    }

    // ---- completion ticket ----
    __threadfence();
    __syncthreads();
    if (tid == 0) s_ticket = atomicAdd(&g_cnt[blockIdx.y], 1u);
    __syncthreads();
    const unsigned ticket = s_ticket;
    if (ticket < 120u) return;

    // ---- fused softmax tail: last 8 finishers normalize 16 rows each ----
    if (tid == 0) {
        unsigned c;
        do {
            asm volatile("ld.acquire.gpu.u32 %0, [%1];"
                         : "=r"(c) : "l"(&g_cnt[blockIdx.y]) : "memory");
            if (c < 128u) __nanosleep(200);
        } while (c < 128u);
    }
    __syncthreads();

    // combine stats: warp w handles one row
    __shared__ float s_m[16], s_inv[16];
    const int idx8 = (int)ticket - 120;
    {
        int row = qBase + idx8 * 16 + w;
        float mv[4], lv[4];
        float m = -3.0e38f;
#pragma unroll
        for (int j = 0; j < 4; j++) {
            mv[j] = g_pm[(size_t)row * NTILES + lane + j * 32];
            lv[j] = g_pl[(size_t)row * NTILES + lane + j * 32];
            m = fmaxf(m, mv[j]);
        }
#pragma unroll
        for (int o = 16; o; o >>= 1) m = fmaxf(m, __shfl_xor_sync(0xffffffffu, m, o));
        float l = 0.f;
#pragma unroll
        for (int j = 0; j < 4; j++) l += lv[j] * __expf(mv[j] - m);
#pragma unroll
        for (int o = 16; o; o >>= 1) l += __shfl_xor_sync(0xffffffffu, l, o);
        if (lane == 0) {
            s_m[w] = m;
            s_inv[w] = 1.0f / l;
        }
    }
    __syncthreads();

    // normalize 16 rows in place: warp w streams row (qBase + idx8*16 + w)
    {
        int row = qBase + idx8 * 16 + w;
        float m = s_m[w], inv = s_inv[w];
        float4* Wr = (float4*)(W + (size_t)row * NK);
#pragma unroll 4
        for (int i = lane; i < NK / 4; i += 32) {
            float4 t = Wr[i];
            t.x = __expf(t.x - m) * inv;
            t.y = __expf(t.y - m) * inv;
            t.z = __expf(t.z - m) * inv;
            t.w = __expf(t.w - m) * inv;
            Wr[i] = t;
        }
    }
}

// ---------------- kernel 3: X = W V, single fp16 MMA pass (exact R4 pv) ----------------
#define PWS 72
#define PVS 264

__global__ __launch_bounds__(256, 2) void pv_kernel(const float* __restrict__ W,
                                                    float* __restrict__ X) {
    extern __shared__ __half smh[];
    __half* sWf = smh;                 // 64 x 72
    __half* sV = smh + 64 * PWS;       // 2 stages x 64 x 264

    const int tid = threadIdx.x;
    const int lane = tid & 31, w = tid >> 5;
    const int wm = w >> 2, wn = w & 3;
    const int mBase = blockIdx.x * 64;

    float acc[2][8][4];
#pragma unroll
    for (int mi = 0; mi < 2; mi++)
#pragma unroll
        for (int ni = 0; ni < 8; ni++)
#pragma unroll
            for (int j = 0; j < 4; j++) acc[mi][ni][j] = 0.f;

    auto loadV = [&](int s, int k0) {
        __half* vf = sV + s * 64 * PVS;
#pragma unroll
        for (int it = 0; it < 8; it++) {
            int idx = it * 256 + tid;
            int row = idx >> 5, cv = (idx & 31) << 3;
            cp16(vf + row * PVS + cv, g_Vf + (size_t)(k0 + row) * DV + cv);
        }
        cp_commit();
    };

    loadV(0, 0);

    for (int i = 0; i < NK / 64; i++) {
        const int k0 = i * 64;
        if (i < NK / 64 - 1) loadV((i + 1) & 1, k0 + 64);

        // W chunk 64x64 fp32 -> fp16 in smem
#pragma unroll
        for (int it = 0; it < 4; it++) {
            int idx = it * 256 + tid;
            int row = idx >> 4, cv = (idx & 15) << 2;
            float4 t = *(const float4*)&W[(size_t)(mBase + row) * NK + k0 + cv];
            __half2* p = (__half2*)&sWf[row * PWS + cv];
            p[0] = __halves2half2(__float2half_rn(t.x), __float2half_rn(t.y));
            p[1] = __halves2half2(__float2half_rn(t.z), __float2half_rn(t.w));
        }

        if (i < NK / 64 - 1) cp_wait<1>();
        else cp_wait<0>();
        __syncthreads();

        const __half* vf = sV + (i & 1) * 64 * PVS;

#pragma unroll
        for (int ks = 0; ks < 4; ks++) {
            int kk = ks * 16;
            uint32_t a[2][4], b[8][2];
#pragma unroll
            for (int mi = 0; mi < 2; mi++) {
                int m0 = wm * 32 + mi * 16;
                int mat = lane >> 3;
                int r = m0 + ((mat & 1) << 3) + (lane & 7);
                int c = kk + ((mat >> 1) << 3);
                ldsm_x4(a[mi], smem_u32(&sWf[r * PWS + c]));
            }
#pragma unroll
            for (int ni = 0; ni < 8; ni++) {
                int n0 = wn * 64 + ni * 8;
                int mat = (lane >> 3) & 1;
                int r = kk + (mat << 3) + (lane & 7);
                ldsm_x2_trans(b[ni], smem_u32(&vf[r * PVS + n0]));
            }
#pragma unroll
            for (int mi = 0; mi < 2; mi++)
#pragma unroll
                for (int ni = 0; ni < 8; ni++)
                    mma_fp16(acc[mi][ni], a[mi], b[ni]);
        }
        __syncthreads();
    }

#pragma unroll
    for (int mi = 0; mi < 2; mi++) {
        int r0 = mBase + wm * 32 + mi * 16 + (lane >> 2);
#pragma unroll
        for (int ni = 0; ni < 8; ni++) {
            int c0 = wn * 64 + ni * 8 + ((lane & 3) << 1);
            *(float2*)&X[(size_t)r0 * DV + c0] = make_float2(acc[mi][ni][0], acc[mi][ni][1]);
            *(float2*)&X[(size_t)(r0 + 8) * DV + c0] = make_float2(acc[mi][ni][2], acc[mi][ni][3]);
        }
    }
}

// ---------------- launcher ----------------
extern "C" void kernel_launch(void* const* d_in, const int* in_sizes, int n_in,
                              void* d_out, int out_size) {
    const float* Q = (const float*)d_in[0];
    const float* K = (const float*)d_in[1];
    const float* V = (const float*)d_in[2];
    float* X = (float*)d_out;                    // [NQ, DV]
    float* W = (float*)d_out + (size_t)NQ * DV;  // [NQ, NK]

    const int qk_smem = 4 * QK_A * 2;                      // 73728 B
    const int pv_smem = (64 * PWS + 2 * 64 * PVS) * 2;     // 76800 B
    cudaFuncSetAttribute(qk_kernel, cudaFuncAttributeMaxDynamicSharedMemorySize, qk_smem);
    cudaFuncSetAttribute(pv_kernel, cudaFuncAttributeMaxDynamicSharedMemorySize, pv_smem);

    split_all_kernel<<<(NQ * DIM + 255) / 256, 256>>>(Q, K, V);

    dim3 qkGrid(NK / 128, NQ / 128);
    qk_kernel<<<qkGrid, 512, qk_smem>>>(W);

    pv_kernel<<<NQ / 64, 256, pv_smem>>>(W, X);
}

// round 14
// speedup vs baseline: 1.1422x; 1.0450x over previous
#include <cuda_runtime.h>
#include <cuda_bf16.h>
#include <cuda_fp16.h>
#include <cstdint>

#define NQ 16384
#define NK 16384
#define DIM 256
#define DV 256

// ---------------- scratch (static device arrays; no allocations) ----------------
__device__ __nv_bfloat16 g_Qh[NQ * DIM];
__device__ __nv_bfloat16 g_Ql[NQ * DIM];
__device__ __nv_bfloat16 g_Kh[NK * DIM];
__device__ __nv_bfloat16 g_Kl[NK * DIM];
__device__ __half g_Vf[NK * DV];

// ---------------- helpers ----------------
__device__ __forceinline__ unsigned smem_u32(const void* p) {
    return (unsigned)__cvta_generic_to_shared(p);
}
__device__ __forceinline__ void cp16(void* dst, const void* src) {
    unsigned d = smem_u32(dst);
    asm volatile("cp.async.cg.shared.global [%0], [%1], 16;" :: "r"(d), "l"(src));
}
__device__ __forceinline__ void cp_commit() {
    asm volatile("cp.async.commit_group;");
}
template <int N>
__device__ __forceinline__ void cp_wait() {
    asm volatile("cp.async.wait_group %0;" :: "n"(N));
}
__device__ __forceinline__ void ldsm_x4(uint32_t* r, unsigned addr) {
    asm volatile("ldmatrix.sync.aligned.m8n8.x4.shared.b16 {%0,%1,%2,%3}, [%4];"
                 : "=r"(r[0]), "=r"(r[1]), "=r"(r[2]), "=r"(r[3]) : "r"(addr));
}
__device__ __forceinline__ void ldsm_x2(uint32_t* r, unsigned addr) {
    asm volatile("ldmatrix.sync.aligned.m8n8.x2.shared.b16 {%0,%1}, [%2];"
                 : "=r"(r[0]), "=r"(r[1]) : "r"(addr));
}
__device__ __forceinline__ void ldsm_x2_trans(uint32_t* r, unsigned addr) {
    asm volatile("ldmatrix.sync.aligned.m8n8.x2.trans.shared.b16 {%0,%1}, [%2];"
                 : "=r"(r[0]), "=r"(r[1]) : "r"(addr));
}
__device__ __forceinline__ void mma_bf16(float* c, const uint32_t* a, const uint32_t* b) {
    asm volatile(
        "mma.sync.aligned.m16n8k16.row.col.f32.bf16.bf16.f32 "
        "{%0,%1,%2,%3},{%4,%5,%6,%7},{%8,%9},{%0,%1,%2,%3};"
        : "+f"(c[0]), "+f"(c[1]), "+f"(c[2]), "+f"(c[3])
        : "r"(a[0]), "r"(a[1]), "r"(a[2]), "r"(a[3]), "r"(b[0]), "r"(b[1]));
}
__device__ __forceinline__ void mma_fp16(float* c, const uint32_t* a, const uint32_t* b) {
    asm volatile(
        "mma.sync.aligned.m16n8k16.row.col.f32.f16.f16.f32 "
        "{%0,%1,%2,%3},{%4,%5,%6,%7},{%8,%9},{%0,%1,%2,%3};"
        : "+f"(c[0]), "+f"(c[1]), "+f"(c[2]), "+f"(c[3])
        : "r"(a[0]), "r"(a[1]), "r"(a[2]), "r"(a[3]), "r"(b[0]), "r"(b[1]));
}

// ---------------- kernel 1: splits (Q,K -> bf16 hi/lo; V -> fp16) ----------------
__global__ void split_all_kernel(const float* __restrict__ Q,
                                 const float* __restrict__ K,
                                 const float* __restrict__ V) {
    int i = blockIdx.x * blockDim.x + threadIdx.x;
    if (i < NQ * DIM) {
        float q = Q[i];
        __nv_bfloat16 qh = __float2bfloat16(q);
        g_Qh[i] = qh;
        g_Ql[i] = __float2bfloat16(q - __bfloat162float(qh));
        float k = K[i];
        __nv_bfloat16 kh = __float2bfloat16(k);
        g_Kh[i] = kh;
        g_Kl[i] = __float2bfloat16(k - __bfloat162float(kh));
        g_Vf[i] = __float2half_rn(V[i]);
    }
}

// ---------------- kernel 2: S = Q K^T, 2 CTAs/SM ----------------
// CTA tile 128(q) x 64(k), 256 threads, 8 warps 4(m)x2(n), warp tile 32x32.
// __launch_bounds__(256,2): two co-resident CTAs per SM with independent barriers,
// so one CTA's smem-load phase hides under the other's MMA phase.
// S = Qh*Kh + Qh*Kl + Ql*Kh (error-compensated bf16).
#define QKS 72  // smem row stride in bf16 (64 + 8 pad)

__global__ __launch_bounds__(256, 2) void qk_kernel(float* __restrict__ W) {
    extern __shared__ __nv_bfloat16 sm[];
    __nv_bfloat16* sQh = sm;                    // 128 x 72
    __nv_bfloat16* sQl = sm + 128 * QKS;        // 128 x 72
    __nv_bfloat16* sKh = sm + 2 * 128 * QKS;    // 64 x 72
    __nv_bfloat16* sKl = sm + 2 * 128 * QKS + 64 * QKS;

    const int tid = threadIdx.x;
    const int lane = tid & 31, w = tid >> 5;
    const int wm = w >> 1, wn = w & 1;
    const int qBase = blockIdx.y * 128;
    const int kBase = blockIdx.x * 64;

    float acc[2][4][4];
#pragma unroll
    for (int mi = 0; mi < 2; mi++)
#pragma unroll
        for (int ni = 0; ni < 4; ni++)
#pragma unroll
            for (int j = 0; j < 4; j++) acc[mi][ni][j] = 0.f;

    for (int kc = 0; kc < DIM; kc += 64) {
        // Q tiles: 128x64 bf16 (h,l) = 1024 uint4 each; 256 thr -> 4 iters each
#pragma unroll
        for (int it = 0; it < 4; it++) {
            int idx = it * 256 + tid;
            int row = idx >> 3, cv = (idx & 7) << 3;
            size_t gq = (size_t)(qBase + row) * DIM + kc + cv;
            *(uint4*)&sQh[row * QKS + cv] = *(const uint4*)&g_Qh[gq];
            *(uint4*)&sQl[row * QKS + cv] = *(const uint4*)&g_Ql[gq];
        }
        // K tiles: 64x64 bf16 (h,l) = 512 uint4 each; 2 iters each
#pragma unroll
        for (int it = 0; it < 2; it++) {
            int idx = it * 256 + tid;
            int row = idx >> 3, cv = (idx & 7) << 3;
            size_t gk = (size_t)(kBase + row) * DIM + kc + cv;
            *(uint4*)&sKh[row * QKS + cv] = *(const uint4*)&g_Kh[gk];
            *(uint4*)&sKl[row * QKS + cv] = *(const uint4*)&g_Kl[gk];
        }
        __syncthreads();

#pragma unroll
        for (int ks = 0; ks < 4; ks++) {
            const int k0 = ks * 16;
            uint32_t ah[2][4], al[2][4], bh[4][2], bl[4][2];
#pragma unroll
            for (int mi = 0; mi < 2; mi++) {
                int m0 = wm * 32 + mi * 16;
                int mat = lane >> 3;
                int r = m0 + ((mat & 1) << 3) + (lane & 7);
                int c = k0 + ((mat >> 1) << 3);
                ldsm_x4(ah[mi], smem_u32(&sQh[r * QKS + c]));
                ldsm_x4(al[mi], smem_u32(&sQl[r * QKS + c]));
            }
#pragma unroll
            for (int ni = 0; ni < 4; ni++) {
                int n0 = wn * 32 + ni * 8;
                int mat = (lane >> 3) & 1;
                int r = n0 + (lane & 7);
                int c = k0 + (mat << 3);
                ldsm_x2(bh[ni], smem_u32(&sKh[r * QKS + c]));
                ldsm_x2(bl[ni], smem_u32(&sKl[r * QKS + c]));
            }
#pragma unroll
            for (int mi = 0; mi < 2; mi++)
#pragma unroll
                for (int ni = 0; ni < 4; ni++) {
                    mma_bf16(acc[mi][ni], ah[mi], bh[ni]);
                    mma_bf16(acc[mi][ni], ah[mi], bl[ni]);
                    mma_bf16(acc[mi][ni], al[mi], bh[ni]);
                }
        }
        __syncthreads();
    }

#pragma unroll
    for (int mi = 0; mi < 2; mi++) {
        int r0 = qBase + wm * 32 + mi * 16 + (lane >> 2);
#pragma unroll
        for (int ni = 0; ni < 4; ni++) {
            int c0 = kBase + wn * 32 + ni * 8 + ((lane & 3) << 1);
            *(float2*)&W[(size_t)r0 * NK + c0] = make_float2(acc[mi][ni][0], acc[mi][ni][1]);
            *(float2*)&W[(size_t)(r0 + 8) * NK + c0] = make_float2(acc[mi][ni][2], acc[mi][ni][3]);
        }
    }
}

// ---------------- kernel 3: in-place row softmax on W (proven R4 version) ----------------
__global__ __launch_bounds__(256, 1) void softmax_kernel(float* __restrict__ W) {
    extern __shared__ float rowbuf[];
    __shared__ float red[8];
    const int tid = threadIdx.x;
    const int lane = tid & 31, w = tid >> 5;
    float4* Wr = (float4*)(W + (size_t)blockIdx.x * NK);
    float4* R = (float4*)rowbuf;

    float lmax = -3.0e38f;
#pragma unroll
    for (int i = 0; i < 16; i++) {
        int idx = i * 256 + tid;
        float4 t = Wr[idx];
        R[idx] = t;
        lmax = fmaxf(lmax, fmaxf(fmaxf(t.x, t.y), fmaxf(t.z, t.w)));
    }
#pragma unroll
    for (int o = 16; o; o >>= 1) lmax = fmaxf(lmax, __shfl_xor_sync(0xffffffffu, lmax, o));
    if (lane == 0) red[w] = lmax;
    __syncthreads();
    float mx = red[0];
#pragma unroll
    for (int j = 1; j < 8; j++) mx = fmaxf(mx, red[j]);
    __syncthreads();

    float lsum = 0.f;
#pragma unroll
    for (int i = 0; i < 16; i++) {
        int idx = i * 256 + tid;
        float4 t = R[idx];
        t.x = __expf(t.x - mx);
        t.y = __expf(t.y - mx);
        t.z = __expf(t.z - mx);
        t.w = __expf(t.w - mx);
        R[idx] = t;
        lsum += t.x + t.y + t.z + t.w;
    }
#pragma unroll
    for (int o = 16; o; o >>= 1) lsum += __shfl_xor_sync(0xffffffffu, lsum, o);
    if (lane == 0) red[w] = lsum;
    __syncthreads();
    float total = 0.f;
#pragma unroll
    for (int j = 0; j < 8; j++) total += red[j];
    float inv = 1.0f / total;

#pragma unroll
    for (int i = 0; i < 16; i++) {
        int idx = i * 256 + tid;
        float4 t = R[idx];
        t.x *= inv; t.y *= inv; t.z *= inv; t.w *= inv;
        Wr[idx] = t;
    }
}

// ---------------- kernel 4: X = W V, single fp16 MMA pass (exact R4 pv) ----------------
#define PWS 72
#define PVS 264

__global__ __launch_bounds__(256, 2) void pv_kernel(const float* __restrict__ W,
                                                    float* __restrict__ X) {
    extern __shared__ __half smh[];
    __half* sWf = smh;                 // 64 x 72
    __half* sV = smh + 64 * PWS;       // 2 stages x 64 x 264

    const int tid = threadIdx.x;
    const int lane = tid & 31, w = tid >> 5;
    const int wm = w >> 2, wn = w & 3;
    const int mBase = blockIdx.x * 64;

    float acc[2][8][4];
#pragma unroll
    for (int mi = 0; mi < 2; mi++)
#pragma unroll
        for (int ni = 0; ni < 8; ni++)
#pragma unroll
            for (int j = 0; j < 4; j++) acc[mi][ni][j] = 0.f;

    auto loadV = [&](int s, int k0) {
        __half* vf = sV + s * 64 * PVS;
#pragma unroll
        for (int it = 0; it < 8; it++) {
            int idx = it * 256 + tid;
            int row = idx >> 5, cv = (idx & 31) << 3;
            cp16(vf + row * PVS + cv, g_Vf + (size_t)(k0 + row) * DV + cv);
        }
        cp_commit();
    };

    loadV(0, 0);

    for (int i = 0; i < NK / 64; i++) {
        const int k0 = i * 64;
        if (i < NK / 64 - 1) loadV((i + 1) & 1, k0 + 64);

        // W chunk 64x64 fp32 -> fp16 in smem
#pragma unroll
        for (int it = 0; it < 4; it++) {
            int idx = it * 256 + tid;
            int row = idx >> 4, cv = (idx & 15) << 2;
            float4 t = *(const float4*)&W[(size_t)(mBase + row) * NK + k0 + cv];
            __half2* p = (__half2*)&sWf[row * PWS + cv];
            p[0] = __halves2half2(__float2half_rn(t.x), __float2half_rn(t.y));
            p[1] = __halves2half2(__float2half_rn(t.z), __float2half_rn(t.w));
        }

        if (i < NK / 64 - 1) cp_wait<1>();
        else cp_wait<0>();
        __syncthreads();

        const __half* vf = sV + (i & 1) * 64 * PVS;

#pragma unroll
        for (int ks = 0; ks < 4; ks++) {
            int kk = ks * 16;
            uint32_t a[2][4], b[8][2];
#pragma unroll
            for (int mi = 0; mi < 2; mi++) {
                int m0 = wm * 32 + mi * 16;
                int mat = lane >> 3;
                int r = m0 + ((mat & 1) << 3) + (lane & 7);
                int c = kk + ((mat >> 1) << 3);
                ldsm_x4(a[mi], smem_u32(&sWf[r * PWS + c]));
            }
#pragma unroll
            for (int ni = 0; ni < 8; ni++) {
                int n0 = wn * 64 + ni * 8;
                int mat = (lane >> 3) & 1;
                int r = kk + (mat << 3) + (lane & 7);
                ldsm_x2_trans(b[ni], smem_u32(&vf[r * PVS + n0]));
            }
#pragma unroll
            for (int mi = 0; mi < 2; mi++)
#pragma unroll
                for (int ni = 0; ni < 8; ni++)
                    mma_fp16(acc[mi][ni], a[mi], b[ni]);
        }
        __syncthreads();
    }

#pragma unroll
    for (int mi = 0; mi < 2; mi++) {
        int r0 = mBase + wm * 32 + mi * 16 + (lane >> 2);
#pragma unroll
        for (int ni = 0; ni < 8; ni++) {
            int c0 = wn * 64 + ni * 8 + ((lane & 3) << 1);
            *(float2*)&X[(size_t)r0 * DV + c0] = make_float2(acc[mi][ni][0], acc[mi][ni][1]);
            *(float2*)&X[(size_t)(r0 + 8) * DV + c0] = make_float2(acc[mi][ni][2], acc[mi][ni][3]);
        }
    }
}

// ---------------- launcher ----------------
extern "C" void kernel_launch(void* const* d_in, const int* in_sizes, int n_in,
                              void* d_out, int out_size) {
    const float* Q = (const float*)d_in[0];
    const float* K = (const float*)d_in[1];
    const float* V = (const float*)d_in[2];
    float* X = (float*)d_out;                    // [NQ, DV]
    float* W = (float*)d_out + (size_t)NQ * DV;  // [NQ, NK]

    const int qk_smem = (2 * 128 * QKS + 2 * 64 * QKS) * 2;  // 55296 B -> 2 CTAs/SM
    const int sm_smem = NK * 4;                              // 65536 B
    const int pv_smem = (64 * PWS + 2 * 64 * PVS) * 2;       // 76800 B
    cudaFuncSetAttribute(qk_kernel, cudaFuncAttributeMaxDynamicSharedMemorySize, qk_smem);
    cudaFuncSetAttribute(softmax_kernel, cudaFuncAttributeMaxDynamicSharedMemorySize, sm_smem);
    cudaFuncSetAttribute(pv_kernel, cudaFuncAttributeMaxDynamicSharedMemorySize, pv_smem);

    split_all_kernel<<<(NQ * DIM + 255) / 256, 256>>>(Q, K, V);

    dim3 qkGrid(NK / 64, NQ / 128);
    qk_kernel<<<qkGrid, 256, qk_smem>>>(W);

    softmax_kernel<<<NQ, 256, sm_smem>>>(W);

    pv_kernel<<<NQ / 64, 256, pv_smem>>>(W, X);
}